// round 15
// baseline (speedup 1.0000x reference)
#include <cuda_runtime.h>
#include <cuda_bf16.h>
#include <mma.h>
#include <math.h>

using namespace nvcuda;

#define NN      100000
#define NN_PAD  100096          // 782 * 128, zero pad for unguarded fragment loads
#define EE      1600000
#define DIM     128

// Scratch (static device globals: no allocations allowed; zero-initialized)
__device__ float g_dis[NN];
__device__ float g_h [(size_t)NN * DIM];                 // hs = (A@W)*dis (fp32)
__device__ __nv_bfloat16 g_ah[(size_t)NN_PAD * DIM];     // activation hi (bf16), zero-padded
__device__ __nv_bfloat16 g_al[(size_t)NN_PAD * DIM];     // activation lo (bf16), zero-padded
__device__ int   g_cnt[NN];
__device__ int   g_rowptr[NN + 1];
__device__ int   g_cursor[NN];
__device__ int   g_colsrc[EE];
__device__ int   g_blocksum[1024];
// Split weights (bf16 hi/lo), natural [K=128][N] layout
__device__ __nv_bfloat16 g_W0h[16384], g_W0l[16384];
__device__ __nv_bfloat16 g_W1h[16384], g_W1l[16384];
__device__ __nv_bfloat16 g_W2h[8192],  g_W2l[8192];

__device__ __forceinline__ void split_bf16(float v, __nv_bfloat16& h, __nv_bfloat16& l) {
    h = __float2bfloat16(v);
    l = __float2bfloat16(v - __bfloat162float(h));
}

// ---------------------------------------------------------------------------
// Fused prep: x -> (Xh,Xl) + W0 -> (W0h,W0l)
// ---------------------------------------------------------------------------
__global__ void split_xw0_kernel(const float* __restrict__ X, const float* __restrict__ W0,
                                 __nv_bfloat16* __restrict__ Xh, __nv_bfloat16* __restrict__ Xl,
                                 __nv_bfloat16* __restrict__ Wh, __nv_bfloat16* __restrict__ Wl,
                                 int x4) {
    int i = blockIdx.x * blockDim.x + threadIdx.x;
    if (i < x4) {
        float4 v = ((const float4*)X)[i];
        __nv_bfloat16 h0, h1, h2, h3, l0, l1, l2, l3;
        split_bf16(v.x, h0, l0); split_bf16(v.y, h1, l1);
        split_bf16(v.z, h2, l2); split_bf16(v.w, h3, l3);
        ((__nv_bfloat162*)Xh)[2 * i]     = __nv_bfloat162(h0, h1);
        ((__nv_bfloat162*)Xh)[2 * i + 1] = __nv_bfloat162(h2, h3);
        ((__nv_bfloat162*)Xl)[2 * i]     = __nv_bfloat162(l0, l1);
        ((__nv_bfloat162*)Xl)[2 * i + 1] = __nv_bfloat162(l2, l3);
    } else {
        int j = i - x4;
        if (j < 16384) {
            __nv_bfloat16 h, l;
            split_bf16(W0[j], h, l);
            Wh[j] = h; Wl[j] = l;
        }
    }
}

__global__ void split_w_kernel(const float* __restrict__ W, __nv_bfloat16* __restrict__ Wh,
                               __nv_bfloat16* __restrict__ Wl, int n) {
    int i = blockIdx.x * blockDim.x + threadIdx.x;
    if (i < n) {
        __nv_bfloat16 h, l;
        split_bf16(W[i], h, l);
        Wh[i] = h; Wl[i] = l;
    }
}

__global__ void count_kernel(const int* __restrict__ dst, int* cnt, int e) {
    int i = blockIdx.x * blockDim.x + threadIdx.x;
    if (i < e) atomicAdd(&cnt[dst[i]], 1);
}

__global__ void dis_kernel(const int* __restrict__ cnt, float* __restrict__ dis, int n) {
    int i = blockIdx.x * blockDim.x + threadIdx.x;
    if (i < n) dis[i] = rsqrtf((float)cnt[i] + 1.0f);
}

// ---------------------------------------------------------------------------
// Multi-block exclusive scan + CSR fill
// ---------------------------------------------------------------------------
__global__ __launch_bounds__(1024) void scan_block_kernel(const int* __restrict__ cnt,
                                                          int* __restrict__ rowptr,
                                                          int* __restrict__ blocksum, int n) {
    __shared__ int wsum[32];
    const int tid = threadIdx.x, lane = tid & 31, wid = tid >> 5;
    int i = blockIdx.x * 1024 + tid;
    int v = (i < n) ? cnt[i] : 0;
    int x = v;
#pragma unroll
    for (int off = 1; off < 32; off <<= 1) {
        int t = __shfl_up_sync(0xffffffffu, x, off);
        if (lane >= off) x += t;
    }
    if (lane == 31) wsum[wid] = x;
    __syncthreads();
    if (wid == 0) {
        int w = wsum[lane];
#pragma unroll
        for (int off = 1; off < 32; off <<= 1) {
            int t = __shfl_up_sync(0xffffffffu, w, off);
            if (lane >= off) w += t;
        }
        wsum[lane] = w;
    }
    __syncthreads();
    int excl = x - v + (wid ? wsum[wid - 1] : 0);
    if (i < n) rowptr[i] = excl;
    if (tid == 1023) blocksum[blockIdx.x] = wsum[31];
}

__global__ void scan_carry_kernel(int* blocksum, int nb) {
    if (threadIdx.x == 0) {
        int acc = 0;
        for (int i = 0; i < nb; i++) { int v = blocksum[i]; blocksum[i] = acc; acc += v; }
    }
}

__global__ void scan_add_kernel(int* __restrict__ rowptr, const int* __restrict__ blocksum,
                                int* __restrict__ cnt, int* __restrict__ cur, int n, int e) {
    int i = blockIdx.x * blockDim.x + threadIdx.x;
    if (i < n) {
        int r = rowptr[i] + blocksum[i >> 10];
        rowptr[i] = r;
        cur[i]    = r;
        cnt[i]    = 0;
    }
    if (i == 0) rowptr[n] = e;
}

__global__ void fill_kernel(const int* __restrict__ src, const int* __restrict__ dst,
                            int* __restrict__ cur, int* __restrict__ colsrc, int e) {
    int i = blockIdx.x * blockDim.x + threadIdx.x;
    if (i < e) {
        int pos = atomicAdd(&cur[dst[i]], 1);
        colsrc[pos] = src[i];
    }
}

// ---------------------------------------------------------------------------
// GEMM v4 (barrier-free mainloop):
//   C = A[M,128] @ W[128,BN] ; hs = C * dis[row]
// A (hi/lo bf16, padded gmem) loaded per-warp via wmma fragments -- no smem,
// no mainloop syncthreads. W (hi/lo) staged to smem once.
// 256 threads = 8 warps (4m x 2n), warp tile 32 x (BN/2).
// ---------------------------------------------------------------------------
template <int BN>
__global__ __launch_bounds__(256, 2) void gemm_tc_kernel(
    const __nv_bfloat16* __restrict__ Ah_g,
    const __nv_bfloat16* __restrict__ Al_g,
    const __nv_bfloat16* __restrict__ Bh_g,
    const __nv_bfloat16* __restrict__ Bl_g,
    const float* __restrict__ dis,
    float* __restrict__ hs_out, int M)
{
    constexpr int WN  = BN / 2;
    constexpr int FN  = WN / 16;
    constexpr int LDB = BN + 8;

    extern __shared__ __align__(16) unsigned char smem_raw[];
    __nv_bfloat16* Bh = (__nv_bfloat16*)smem_raw;        // 128 x LDB
    __nv_bfloat16* Bl = Bh + 128 * LDB;

    const int tid  = threadIdx.x;
    const int wid  = tid >> 5;
    const int wm   = wid & 3;          // warp row (x32)
    const int wn   = wid >> 2;         // warp col (x WN)
    const int row0 = blockIdx.x * 128;

    // Stage full W (hi/lo) once
    constexpr int ELEMS = 128 * BN;
    for (int e = tid * 8; e < ELEMS; e += 256 * 8) {
        int r = e / BN, c = e % BN;
        *(uint4*)&Bh[r * LDB + c] = *(const uint4*)&Bh_g[e];
        *(uint4*)&Bl[r * LDB + c] = *(const uint4*)&Bl_g[e];
    }
    __syncthreads();

    wmma::fragment<wmma::accumulator, 16, 16, 16, float> acc[2][FN];
#pragma unroll
    for (int i = 0; i < 2; i++)
#pragma unroll
        for (int j = 0; j < FN; j++) wmma::fill_fragment(acc[i][j], 0.f);

    const __nv_bfloat16* Ah0 = Ah_g + (size_t)(row0 + wm * 32) * 128;
    const __nv_bfloat16* Al0 = Al_g + (size_t)(row0 + wm * 32) * 128;

    for (int s = 0; s < 8; s++) {
        wmma::fragment<wmma::matrix_a, 16, 16, 16, __nv_bfloat16, wmma::row_major> fa_h[2], fa_l[2];
#pragma unroll
        for (int i = 0; i < 2; i++) {
            wmma::load_matrix_sync(fa_h[i], Ah0 + (size_t)(i * 16) * 128 + s * 16, 128);
            wmma::load_matrix_sync(fa_l[i], Al0 + (size_t)(i * 16) * 128 + s * 16, 128);
        }
#pragma unroll
        for (int j = 0; j < FN; j++) {
            wmma::fragment<wmma::matrix_b, 16, 16, 16, __nv_bfloat16, wmma::row_major> fb_h, fb_l;
            wmma::load_matrix_sync(fb_h, Bh + (s * 16) * LDB + wn * WN + j * 16, LDB);
            wmma::load_matrix_sync(fb_l, Bl + (s * 16) * LDB + wn * WN + j * 16, LDB);
#pragma unroll
            for (int i = 0; i < 2; i++) {
                wmma::mma_sync(acc[i][j], fa_h[i], fb_h, acc[i][j]);
                wmma::mma_sync(acc[i][j], fa_h[i], fb_l, acc[i][j]);
                wmma::mma_sync(acc[i][j], fa_l[i], fb_h, acc[i][j]);
            }
        }
    }

    // Epilogue: stage C in smem (reuses W region), scaled write
    __syncthreads();
    float* Cs = (float*)smem_raw;
#pragma unroll
    for (int i = 0; i < 2; i++)
#pragma unroll
        for (int j = 0; j < FN; j++)
            wmma::store_matrix_sync(Cs + (wm * 32 + i * 16) * BN + wn * WN + j * 16,
                                    acc[i][j], BN, wmma::mem_row_major);
    __syncthreads();

    constexpr int QB = BN / 4;
    for (int i = tid; i < 128 * QB; i += 256) {
        int r = i / QB, c = (i % QB) * 4;
        int row = row0 + r;
        if (row < M) {
            float dd = __ldg(dis + row);
            float4 o = *(float4*)&Cs[r * BN + c];
            o.x *= dd; o.y *= dd; o.z *= dd; o.w *= dd;
            *(float4*)(hs_out + (size_t)row * BN + c) = o;
        }
    }
}

// ---------------------------------------------------------------------------
// Aggregation + combine (CSR segment sum), emits bf16 hi/lo activations:
//   v = relu( dis[d]*( hs[d,f] + sum hs[src,f] ) + b[f] ) ; (Ah,Al) = split(v)
// ---------------------------------------------------------------------------
__global__ __launch_bounds__(128) void agg_combine_kernel(
    const float* __restrict__ hs, const int* __restrict__ rowptr,
    const int* __restrict__ colsrc, const float* __restrict__ dis,
    const float* __restrict__ bias,
    __nv_bfloat16* __restrict__ outH, __nv_bfloat16* __restrict__ outL, int n)
{
    constexpr int F = 128;
    int node = blockIdx.x;
    int f    = threadIdx.x;
    int beg  = __ldg(rowptr + node);
    int end  = __ldg(rowptr + node + 1);

    float s0 = __ldg(hs + (size_t)node * F + f);
    float s1 = 0.f, s2 = 0.f, s3 = 0.f;
    int p = beg;
    for (; p + 4 <= end; p += 4) {
        int i0 = __ldg(colsrc + p + 0);
        int i1 = __ldg(colsrc + p + 1);
        int i2 = __ldg(colsrc + p + 2);
        int i3 = __ldg(colsrc + p + 3);
        s0 += __ldg(hs + (size_t)i0 * F + f);
        s1 += __ldg(hs + (size_t)i1 * F + f);
        s2 += __ldg(hs + (size_t)i2 * F + f);
        s3 += __ldg(hs + (size_t)i3 * F + f);
    }
    for (; p < end; ++p)
        s0 += __ldg(hs + (size_t)__ldg(colsrc + p) * F + f);

    float v = fmaxf(fmaf(__ldg(dis + node), (s0 + s1) + (s2 + s3), __ldg(bias + f)), 0.f);
    __nv_bfloat16 h, l;
    split_bf16(v, h, l);
    outH[(size_t)node * F + f] = h;
    outL[(size_t)node * F + f] = l;
}

// ---------------------------------------------------------------------------
// Fused final layer: aggregation + combine + relu + log_softmax (F=64)
// ---------------------------------------------------------------------------
__global__ __launch_bounds__(64) void agg_lsm_kernel(
    const float* __restrict__ hs, const int* __restrict__ rowptr,
    const int* __restrict__ colsrc, const float* __restrict__ dis,
    const float* __restrict__ bias, float* __restrict__ out, int n)
{
    constexpr int F = 64;
    int node = blockIdx.x;
    int f    = threadIdx.x;
    int lane = f & 31, w = f >> 5;
    int beg  = __ldg(rowptr + node);
    int end  = __ldg(rowptr + node + 1);

    float s0 = __ldg(hs + (size_t)node * F + f);
    float s1 = 0.f, s2 = 0.f, s3 = 0.f;
    int p = beg;
    for (; p + 4 <= end; p += 4) {
        int i0 = __ldg(colsrc + p + 0);
        int i1 = __ldg(colsrc + p + 1);
        int i2 = __ldg(colsrc + p + 2);
        int i3 = __ldg(colsrc + p + 3);
        s0 += __ldg(hs + (size_t)i0 * F + f);
        s1 += __ldg(hs + (size_t)i1 * F + f);
        s2 += __ldg(hs + (size_t)i2 * F + f);
        s3 += __ldg(hs + (size_t)i3 * F + f);
    }
    for (; p < end; ++p)
        s0 += __ldg(hs + (size_t)__ldg(colsrc + p) * F + f);

    float v = fmaxf(fmaf(__ldg(dis + node), (s0 + s1) + (s2 + s3), __ldg(bias + f)), 0.f);

    __shared__ float sred[2];
    float m = v;
#pragma unroll
    for (int off = 16; off > 0; off >>= 1)
        m = fmaxf(m, __shfl_xor_sync(0xffffffffu, m, off));
    if (lane == 0) sred[w] = m;
    __syncthreads();
    float M2 = fmaxf(sred[0], sred[1]);
    __syncthreads();

    float e = expf(v - M2);
    float s = e;
#pragma unroll
    for (int off = 16; off > 0; off >>= 1)
        s += __shfl_xor_sync(0xffffffffu, s, off);
    if (lane == 0) sred[w] = s;
    __syncthreads();
    float S = sred[0] + sred[1];

    out[(size_t)node * F + f] = v - M2 - logf(S);
}

// ---------------------------------------------------------------------------
// Launch (single stream; gemm0 is the 4th kernel launch for ncu capture)
// ---------------------------------------------------------------------------
extern "C" void kernel_launch(void* const* d_in, const int* in_sizes, int n_in,
                              void* d_out, int out_size) {
    const float* x  = (const float*)d_in[0];
    const int*   ei = (const int*)d_in[1];
    const float* W0 = (const float*)d_in[2];
    const float* b0 = (const float*)d_in[3];
    const float* W1 = (const float*)d_in[4];
    const float* b1 = (const float*)d_in[5];
    const float* W2 = (const float*)d_in[6];
    const float* b2 = (const float*)d_in[7];
    float* out = (float*)d_out;

    const int E = in_sizes[1] / 2;
    const int N = in_sizes[0] / DIM;
    const int* src = ei;
    const int* dst = ei + E;

    float *p_dis, *p_h;
    __nv_bfloat16 *p_ah, *p_al;
    int *p_cnt, *p_rowptr, *p_cursor, *p_colsrc, *p_blocksum;
    __nv_bfloat16 *p_W0h, *p_W0l, *p_W1h, *p_W1l, *p_W2h, *p_W2l;
    cudaGetSymbolAddress((void**)&p_dis,      g_dis);
    cudaGetSymbolAddress((void**)&p_h,        g_h);
    cudaGetSymbolAddress((void**)&p_ah,       g_ah);
    cudaGetSymbolAddress((void**)&p_al,       g_al);
    cudaGetSymbolAddress((void**)&p_cnt,      g_cnt);
    cudaGetSymbolAddress((void**)&p_rowptr,   g_rowptr);
    cudaGetSymbolAddress((void**)&p_cursor,   g_cursor);
    cudaGetSymbolAddress((void**)&p_colsrc,   g_colsrc);
    cudaGetSymbolAddress((void**)&p_blocksum, g_blocksum);
    cudaGetSymbolAddress((void**)&p_W0h, g_W0h); cudaGetSymbolAddress((void**)&p_W0l, g_W0l);
    cudaGetSymbolAddress((void**)&p_W1h, g_W1h); cudaGetSymbolAddress((void**)&p_W1l, g_W1l);
    cudaGetSymbolAddress((void**)&p_W2h, g_W2h); cudaGetSymbolAddress((void**)&p_W2l, g_W2l);

    const int smem128 = 2 * 128 * (128 + 8) * 2;   // 69632 B
    const int smem64  = 2 * 128 * (64 + 8)  * 2;   // 36864 B
    cudaFuncSetAttribute(gemm_tc_kernel<128>, cudaFuncAttributeMaxDynamicSharedMemorySize, smem128);
    cudaFuncSetAttribute(gemm_tc_kernel<64>,  cudaFuncAttributeMaxDynamicSharedMemorySize, smem64);

    const int T = 256;
    const int nb = (N + 1023) / 1024;
    const int gemm_blocks = (N + 127) / 128;
    const int x4 = N * 32;
    const int sx = x4 + 16384;

    // 1-3: gemm0 prerequisites
    count_kernel<<<(E + T - 1) / T, T>>>(dst, p_cnt, E);                          // 1
    dis_kernel<<<(N + T - 1) / T, T>>>(p_cnt, p_dis, N);                          // 2
    split_xw0_kernel<<<(sx + T - 1) / T, T>>>(x, W0, p_ah, p_al, p_W0h, p_W0l, x4); // 3

    // 4: layer-0 GEMM (ncu captures the 4th launch)
    gemm_tc_kernel<128><<<gemm_blocks, 256, smem128>>>(p_ah, p_al, p_W0h, p_W0l,
                                                       p_dis, p_h, N);            // 4

    // remaining weight splits + CSR build
    split_w_kernel<<<64, 256>>>(W1, p_W1h, p_W1l, 16384);
    split_w_kernel<<<32, 256>>>(W2, p_W2h, p_W2l, 8192);
    scan_block_kernel<<<nb, 1024>>>(p_cnt, p_rowptr, p_blocksum, N);
    scan_carry_kernel<<<1, 32>>>(p_blocksum, nb);
    scan_add_kernel<<<(N + T - 1) / T, T>>>(p_rowptr, p_blocksum, p_cnt, p_cursor, N, E);
    fill_kernel<<<(E + T - 1) / T, T>>>(src, dst, p_cursor, p_colsrc, E);

    // Layer 0 combine -> (Ah, Al)
    agg_combine_kernel<<<N, 128>>>(p_h, p_rowptr, p_colsrc, p_dis, b0, p_ah, p_al, N);

    // Layer 1
    gemm_tc_kernel<128><<<gemm_blocks, 256, smem128>>>(p_ah, p_al, p_W1h, p_W1l,
                                                       p_dis, p_h, N);
    agg_combine_kernel<<<N, 128>>>(p_h, p_rowptr, p_colsrc, p_dis, b1, p_ah, p_al, N);

    // Layer 2 (64 cols) + fused log_softmax
    gemm_tc_kernel<64><<<gemm_blocks, 256, smem64>>>(p_ah, p_al, p_W2h, p_W2l,
                                                     p_dis, p_h, N);
    agg_lsm_kernel<<<N, 64>>>(p_h, p_rowptr, p_colsrc, p_dis, b2, out, N);
}

// round 16
// speedup vs baseline: 1.4604x; 1.4604x over previous
#include <cuda_runtime.h>
#include <cuda_bf16.h>
#include <mma.h>
#include <math.h>

using namespace nvcuda;

#define NN   100000
#define EE   1600000
#define DIM  128

// Scratch (static device globals: no allocations allowed; zero-initialized)
__device__ float g_dis[NN];
__device__ float g_h [(size_t)NN * DIM];   // hs = (A@W)*dis of current layer
__device__ float g_a [(size_t)NN * DIM];   // combined activation (next layer input)
__device__ int   g_cnt[NN];                // in-degree histogram (re-zeroed each run)
__device__ int   g_rowptr[NN + 1];
__device__ int   g_cursor[NN];
__device__ int   g_colsrc[EE];
__device__ int   g_blocksum[1024];
// Split weights (bf16 hi/lo)
__device__ __nv_bfloat16 g_W0h[16384], g_W0l[16384];
__device__ __nv_bfloat16 g_W1h[16384], g_W1l[16384];
__device__ __nv_bfloat16 g_W2h[8192],  g_W2l[8192];

__device__ __forceinline__ void split_bf16(float v, __nv_bfloat16& h, __nv_bfloat16& l) {
    h = __float2bfloat16(v);
    l = __float2bfloat16(v - __bfloat162float(h));
}

// ---------------------------------------------------------------------------
// Weight split: W(fp32) -> Wh + Wl (bf16)
// ---------------------------------------------------------------------------
__global__ void split_w_kernel(const float* __restrict__ W, __nv_bfloat16* __restrict__ Wh,
                               __nv_bfloat16* __restrict__ Wl, int n) {
    int i = blockIdx.x * blockDim.x + threadIdx.x;
    if (i < n) {
        __nv_bfloat16 h, l;
        split_bf16(W[i], h, l);
        Wh[i] = h; Wl[i] = l;
    }
}

// in-degree histogram (cnt zero on entry; scan_add re-zeroes it each run)
__global__ void count_kernel(const int* __restrict__ dst, int* cnt, int e) {
    int i = blockIdx.x * blockDim.x + threadIdx.x;
    if (i < e) atomicAdd(&cnt[dst[i]], 1);
}

// dis = rsqrt(deg+1)
__global__ void dis_kernel(const int* __restrict__ cnt, float* __restrict__ dis, int n) {
    int i = blockIdx.x * blockDim.x + threadIdx.x;
    if (i < n) dis[i] = rsqrtf((float)cnt[i] + 1.0f);
}

// ---------------------------------------------------------------------------
// Multi-block exclusive scan + CSR fill
// ---------------------------------------------------------------------------
__global__ __launch_bounds__(1024) void scan_block_kernel(const int* __restrict__ cnt,
                                                          int* __restrict__ rowptr,
                                                          int* __restrict__ blocksum, int n) {
    __shared__ int wsum[32];
    const int tid = threadIdx.x, lane = tid & 31, wid = tid >> 5;
    int i = blockIdx.x * 1024 + tid;
    int v = (i < n) ? cnt[i] : 0;
    int x = v;
#pragma unroll
    for (int off = 1; off < 32; off <<= 1) {
        int t = __shfl_up_sync(0xffffffffu, x, off);
        if (lane >= off) x += t;
    }
    if (lane == 31) wsum[wid] = x;
    __syncthreads();
    if (wid == 0) {
        int w = wsum[lane];
#pragma unroll
        for (int off = 1; off < 32; off <<= 1) {
            int t = __shfl_up_sync(0xffffffffu, w, off);
            if (lane >= off) w += t;
        }
        wsum[lane] = w;
    }
    __syncthreads();
    int excl = x - v + (wid ? wsum[wid - 1] : 0);
    if (i < n) rowptr[i] = excl;
    if (tid == 1023) blocksum[blockIdx.x] = wsum[31];
}

__global__ void scan_carry_kernel(int* blocksum, int nb) {
    if (threadIdx.x == 0) {
        int acc = 0;
        for (int i = 0; i < nb; i++) { int v = blocksum[i]; blocksum[i] = acc; acc += v; }
    }
}

__global__ void scan_add_kernel(int* __restrict__ rowptr, const int* __restrict__ blocksum,
                                int* __restrict__ cnt, int* __restrict__ cur, int n, int e) {
    int i = blockIdx.x * blockDim.x + threadIdx.x;
    if (i < n) {
        int r = rowptr[i] + blocksum[i >> 10];
        rowptr[i] = r;
        cur[i]    = r;
        cnt[i]    = 0;
    }
    if (i == 0) rowptr[n] = e;
}

__global__ void fill_kernel(const int* __restrict__ src, const int* __restrict__ dst,
                            int* __restrict__ cur, int* __restrict__ colsrc, int e) {
    int i = blockIdx.x * blockDim.x + threadIdx.x;
    if (i < e) {
        int pos = atomicAdd(&cur[dst[i]], 1);
        colsrc[pos] = src[i];
    }
}

// ---------------------------------------------------------------------------
// Tensor-core GEMM (R14-measured best: 70.6us for BN=128):
//   C = A[M,128] @ W[128,BN] ; hs = C * dis[row]
// BM=128, 256 threads = 8 warps (4m x 2n), warp tile 32 x (BN/2).
// Full W (hi+lo) staged in smem ONCE; A split per 16-k stage, double-buffered.
// ---------------------------------------------------------------------------
template <int BN>
__global__ __launch_bounds__(256, 2) void gemm_tc_kernel(
    const float* __restrict__ A,
    const __nv_bfloat16* __restrict__ Bh_g,
    const __nv_bfloat16* __restrict__ Bl_g,
    const float* __restrict__ dis,
    float* __restrict__ hs_out, int M)
{
    constexpr int WN  = BN / 2;
    constexpr int FN  = WN / 16;
    constexpr int LDA = 24;
    constexpr int LDB = BN + 8;
    constexpr int ASZ = 128 * LDA;

    extern __shared__ __align__(16) unsigned char smem_raw[];
    __nv_bfloat16* Ab = (__nv_bfloat16*)smem_raw;        // 4 buffers: h0,l0,h1,l1
    __nv_bfloat16* Bh = Ab + 4 * ASZ;
    __nv_bfloat16* Bl = Bh + 128 * LDB;

    const int tid  = threadIdx.x;
    const int wid  = tid >> 5;
    const int wm   = wid & 3;
    const int wn   = wid >> 2;
    const int row0 = blockIdx.x * 128;

    constexpr int ELEMS = 128 * BN;
    for (int e = tid * 8; e < ELEMS; e += 256 * 8) {
        int r = e / BN, c = e % BN;
        *(uint4*)&Bh[r * LDB + c] = *(const uint4*)&Bh_g[e];
        *(uint4*)&Bl[r * LDB + c] = *(const uint4*)&Bl_g[e];
    }

    wmma::fragment<wmma::accumulator, 16, 16, 16, float> acc[2][FN];
#pragma unroll
    for (int i = 0; i < 2; i++)
#pragma unroll
        for (int j = 0; j < FN; j++) wmma::fill_fragment(acc[i][j], 0.f);

    const int ar   = tid >> 1;
    const int ak   = (tid & 1) * 8;
    const int arow = row0 + ar;

    float4 v0 = make_float4(0.f, 0.f, 0.f, 0.f), v1 = v0;
    if (arow < M) {
        v0 = *(const float4*)(A + (size_t)arow * 128 + ak);
        v1 = *(const float4*)(A + (size_t)arow * 128 + ak + 4);
    }

    for (int s = 0; s < 8; s++) {
        __nv_bfloat16* pAh = Ab + (s & 1) * 2 * ASZ;
        __nv_bfloat16* pAl = pAh + ASZ;
        {
            __nv_bfloat16 h, l;
            split_bf16(v0.x, h, l); pAh[ar * LDA + ak + 0] = h; pAl[ar * LDA + ak + 0] = l;
            split_bf16(v0.y, h, l); pAh[ar * LDA + ak + 1] = h; pAl[ar * LDA + ak + 1] = l;
            split_bf16(v0.z, h, l); pAh[ar * LDA + ak + 2] = h; pAl[ar * LDA + ak + 2] = l;
            split_bf16(v0.w, h, l); pAh[ar * LDA + ak + 3] = h; pAl[ar * LDA + ak + 3] = l;
            split_bf16(v1.x, h, l); pAh[ar * LDA + ak + 4] = h; pAl[ar * LDA + ak + 4] = l;
            split_bf16(v1.y, h, l); pAh[ar * LDA + ak + 5] = h; pAl[ar * LDA + ak + 5] = l;
            split_bf16(v1.z, h, l); pAh[ar * LDA + ak + 6] = h; pAl[ar * LDA + ak + 6] = l;
            split_bf16(v1.w, h, l); pAh[ar * LDA + ak + 7] = h; pAl[ar * LDA + ak + 7] = l;
        }
        __syncthreads();

        if (s < 7 && arow < M) {
            v0 = *(const float4*)(A + (size_t)arow * 128 + (s + 1) * 16 + ak);
            v1 = *(const float4*)(A + (size_t)arow * 128 + (s + 1) * 16 + ak + 4);
        }

        wmma::fragment<wmma::matrix_a, 16, 16, 16, __nv_bfloat16, wmma::row_major> fa_h[2], fa_l[2];
#pragma unroll
        for (int i = 0; i < 2; i++) {
            wmma::load_matrix_sync(fa_h[i], pAh + (wm * 32 + i * 16) * LDA, LDA);
            wmma::load_matrix_sync(fa_l[i], pAl + (wm * 32 + i * 16) * LDA, LDA);
        }
#pragma unroll
        for (int j = 0; j < FN; j++) {
            wmma::fragment<wmma::matrix_b, 16, 16, 16, __nv_bfloat16, wmma::row_major> fb_h, fb_l;
            wmma::load_matrix_sync(fb_h, Bh + (s * 16) * LDB + wn * WN + j * 16, LDB);
            wmma::load_matrix_sync(fb_l, Bl + (s * 16) * LDB + wn * WN + j * 16, LDB);
#pragma unroll
            for (int i = 0; i < 2; i++) {
                wmma::mma_sync(acc[i][j], fa_h[i], fb_h, acc[i][j]);
                wmma::mma_sync(acc[i][j], fa_h[i], fb_l, acc[i][j]);
                wmma::mma_sync(acc[i][j], fa_l[i], fb_h, acc[i][j]);
            }
        }
    }

    __syncthreads();
    float* Cs = (float*)smem_raw;
#pragma unroll
    for (int i = 0; i < 2; i++)
#pragma unroll
        for (int j = 0; j < FN; j++)
            wmma::store_matrix_sync(Cs + (wm * 32 + i * 16) * BN + wn * WN + j * 16,
                                    acc[i][j], BN, wmma::mem_row_major);
    __syncthreads();

    constexpr int QB = BN / 4;
    for (int i = tid; i < 128 * QB; i += 256) {
        int r = i / QB, c = (i % QB) * 4;
        int row = row0 + r;
        if (row < M) {
            float dd = __ldg(dis + row);
            float4 o = *(float4*)&Cs[r * BN + c];
            o.x *= dd; o.y *= dd; o.z *= dd; o.w *= dd;
            *(float4*)(hs_out + (size_t)row * BN + c) = o;
        }
    }
}

// ---------------------------------------------------------------------------
// Aggregation + combine, VECTORIZED: one warp per node, float4 per lane.
//   outA[d,:] = relu( dis[d] * ( hs[d,:] + sum_{s in N(d)} hs[s,:] ) + b[:] )
// 4 independent float4 accumulators -> 4 outstanding LDG.128 per lane.
// ---------------------------------------------------------------------------
__device__ __forceinline__ void f4_add(float4& a, const float4 b) {
    a.x += b.x; a.y += b.y; a.z += b.z; a.w += b.w;
}

__global__ __launch_bounds__(256) void agg_combine_kernel(
    const float* __restrict__ hs, const int* __restrict__ rowptr,
    const int* __restrict__ colsrc, const float* __restrict__ dis,
    const float* __restrict__ bias, float* __restrict__ outA, int n)
{
    int node = (blockIdx.x * 256 + threadIdx.x) >> 5;
    int lane = threadIdx.x & 31;
    if (node >= n) return;

    const float4* hs4 = (const float4*)hs;      // row stride = 32 float4
    int beg = __ldg(rowptr + node);
    int end = __ldg(rowptr + node + 1);

    float4 a0 = __ldg(hs4 + (size_t)node * 32 + lane);   // self-loop term
    float4 a1 = make_float4(0.f, 0.f, 0.f, 0.f), a2 = a1, a3 = a1;

    int p = beg;
    for (; p + 4 <= end; p += 4) {
        int i0 = __ldg(colsrc + p + 0);
        int i1 = __ldg(colsrc + p + 1);
        int i2 = __ldg(colsrc + p + 2);
        int i3 = __ldg(colsrc + p + 3);
        float4 v0 = __ldg(hs4 + (size_t)i0 * 32 + lane);
        float4 v1 = __ldg(hs4 + (size_t)i1 * 32 + lane);
        float4 v2 = __ldg(hs4 + (size_t)i2 * 32 + lane);
        float4 v3 = __ldg(hs4 + (size_t)i3 * 32 + lane);
        f4_add(a0, v0); f4_add(a1, v1); f4_add(a2, v2); f4_add(a3, v3);
    }
    for (; p < end; ++p)
        f4_add(a0, __ldg(hs4 + (size_t)__ldg(colsrc + p) * 32 + lane));

    f4_add(a0, a1); f4_add(a2, a3); f4_add(a0, a2);

    float dd = __ldg(dis + node);
    float4 bb = __ldg((const float4*)bias + lane);
    float4 o;
    o.x = fmaxf(fmaf(dd, a0.x, bb.x), 0.f);
    o.y = fmaxf(fmaf(dd, a0.y, bb.y), 0.f);
    o.z = fmaxf(fmaf(dd, a0.z, bb.z), 0.f);
    o.w = fmaxf(fmaf(dd, a0.w, bb.w), 0.f);
    ((float4*)outA)[(size_t)node * 32 + lane] = o;
}

// ---------------------------------------------------------------------------
// Fused final layer, VECTORIZED: warp per node, float2 per lane (F=64).
// agg + combine + relu + log_softmax
// ---------------------------------------------------------------------------
__global__ __launch_bounds__(256) void agg_lsm_kernel(
    const float* __restrict__ hs, const int* __restrict__ rowptr,
    const int* __restrict__ colsrc, const float* __restrict__ dis,
    const float* __restrict__ bias, float* __restrict__ out, int n)
{
    int node = (blockIdx.x * 256 + threadIdx.x) >> 5;
    int lane = threadIdx.x & 31;
    if (node >= n) return;

    const float2* hs2 = (const float2*)hs;      // row stride = 32 float2
    int beg = __ldg(rowptr + node);
    int end = __ldg(rowptr + node + 1);

    float2 a0 = __ldg(hs2 + (size_t)node * 32 + lane);
    float2 a1 = make_float2(0.f, 0.f), a2 = a1, a3 = a1;

    int p = beg;
    for (; p + 4 <= end; p += 4) {
        int i0 = __ldg(colsrc + p + 0);
        int i1 = __ldg(colsrc + p + 1);
        int i2 = __ldg(colsrc + p + 2);
        int i3 = __ldg(colsrc + p + 3);
        float2 v0 = __ldg(hs2 + (size_t)i0 * 32 + lane);
        float2 v1 = __ldg(hs2 + (size_t)i1 * 32 + lane);
        float2 v2 = __ldg(hs2 + (size_t)i2 * 32 + lane);
        float2 v3 = __ldg(hs2 + (size_t)i3 * 32 + lane);
        a0.x += v0.x; a0.y += v0.y; a1.x += v1.x; a1.y += v1.y;
        a2.x += v2.x; a2.y += v2.y; a3.x += v3.x; a3.y += v3.y;
    }
    for (; p < end; ++p) {
        float2 v = __ldg(hs2 + (size_t)__ldg(colsrc + p) * 32 + lane);
        a0.x += v.x; a0.y += v.y;
    }
    float sx = (a0.x + a1.x) + (a2.x + a3.x);
    float sy = (a0.y + a1.y) + (a2.y + a3.y);

    float dd = __ldg(dis + node);
    float2 bb = __ldg((const float2*)bias + lane);
    float v0 = fmaxf(fmaf(dd, sx, bb.x), 0.f);
    float v1 = fmaxf(fmaf(dd, sy, bb.y), 0.f);

    float m = fmaxf(v0, v1);
#pragma unroll
    for (int off = 16; off > 0; off >>= 1)
        m = fmaxf(m, __shfl_xor_sync(0xffffffffu, m, off));
    float s = expf(v0 - m) + expf(v1 - m);
#pragma unroll
    for (int off = 16; off > 0; off >>= 1)
        s += __shfl_xor_sync(0xffffffffu, s, off);
    float ls = logf(s);

    float2 o = make_float2(v0 - m - ls, v1 - m - ls);
    ((float2*)out)[(size_t)node * 32 + lane] = o;
}

// ---------------------------------------------------------------------------
// Launch (single stream; gemm0 is the 4th kernel launch for ncu capture)
// ---------------------------------------------------------------------------
extern "C" void kernel_launch(void* const* d_in, const int* in_sizes, int n_in,
                              void* d_out, int out_size) {
    const float* x  = (const float*)d_in[0];
    const int*   ei = (const int*)d_in[1];
    const float* W0 = (const float*)d_in[2];
    const float* b0 = (const float*)d_in[3];
    const float* W1 = (const float*)d_in[4];
    const float* b1 = (const float*)d_in[5];
    const float* W2 = (const float*)d_in[6];
    const float* b2 = (const float*)d_in[7];
    float* out = (float*)d_out;

    const int E = in_sizes[1] / 2;
    const int N = in_sizes[0] / DIM;
    const int* src = ei;
    const int* dst = ei + E;

    float *p_dis, *p_h, *p_a;
    int *p_cnt, *p_rowptr, *p_cursor, *p_colsrc, *p_blocksum;
    __nv_bfloat16 *p_W0h, *p_W0l, *p_W1h, *p_W1l, *p_W2h, *p_W2l;
    cudaGetSymbolAddress((void**)&p_dis,      g_dis);
    cudaGetSymbolAddress((void**)&p_h,        g_h);
    cudaGetSymbolAddress((void**)&p_a,        g_a);
    cudaGetSymbolAddress((void**)&p_cnt,      g_cnt);
    cudaGetSymbolAddress((void**)&p_rowptr,   g_rowptr);
    cudaGetSymbolAddress((void**)&p_cursor,   g_cursor);
    cudaGetSymbolAddress((void**)&p_colsrc,   g_colsrc);
    cudaGetSymbolAddress((void**)&p_blocksum, g_blocksum);
    cudaGetSymbolAddress((void**)&p_W0h, g_W0h); cudaGetSymbolAddress((void**)&p_W0l, g_W0l);
    cudaGetSymbolAddress((void**)&p_W1h, g_W1h); cudaGetSymbolAddress((void**)&p_W1l, g_W1l);
    cudaGetSymbolAddress((void**)&p_W2h, g_W2h); cudaGetSymbolAddress((void**)&p_W2l, g_W2l);

    const int smem128 = (4 * 128 * 24 + 2 * 128 * 136) * 2;   // 94208 B
    const int smem64  = (4 * 128 * 24 + 2 * 128 * 72)  * 2;   // 61440 B
    cudaFuncSetAttribute(gemm_tc_kernel<128>, cudaFuncAttributeMaxDynamicSharedMemorySize, smem128);
    cudaFuncSetAttribute(gemm_tc_kernel<64>,  cudaFuncAttributeMaxDynamicSharedMemorySize, smem64);

    const int T = 256;
    const int nb = (N + 1023) / 1024;
    const int gemm_blocks = (N + 127) / 128;
    const int agg_blocks  = (N * 32 + T - 1) / T;   // warp per node

    // 1-3: gemm0 prerequisites
    count_kernel<<<(E + T - 1) / T, T>>>(dst, p_cnt, E);                     // 1
    dis_kernel<<<(N + T - 1) / T, T>>>(p_cnt, p_dis, N);                     // 2
    split_w_kernel<<<64, 256>>>(W0, p_W0h, p_W0l, 16384);                    // 3

    // 4: layer-0 GEMM (ncu captures the 4th launch)
    gemm_tc_kernel<128><<<gemm_blocks, 256, smem128>>>(x, p_W0h, p_W0l,
                                                       p_dis, p_h, N);       // 4

    // remaining weight splits + CSR build
    split_w_kernel<<<64, 256>>>(W1, p_W1h, p_W1l, 16384);
    split_w_kernel<<<32, 256>>>(W2, p_W2h, p_W2l, 8192);
    scan_block_kernel<<<nb, 1024>>>(p_cnt, p_rowptr, p_blocksum, N);
    scan_carry_kernel<<<1, 32>>>(p_blocksum, nb);
    scan_add_kernel<<<(N + T - 1) / T, T>>>(p_rowptr, p_blocksum, p_cnt, p_cursor, N, E);
    fill_kernel<<<(E + T - 1) / T, T>>>(src, dst, p_cursor, p_colsrc, E);

    // Layer 0 combine
    agg_combine_kernel<<<agg_blocks, T>>>(p_h, p_rowptr, p_colsrc, p_dis, b0, p_a, N);

    // Layer 1
    gemm_tc_kernel<128><<<gemm_blocks, 256, smem128>>>(p_a, p_W1h, p_W1l, p_dis, p_h, N);
    agg_combine_kernel<<<agg_blocks, T>>>(p_h, p_rowptr, p_colsrc, p_dis, b1, p_a, N);

    // Layer 2 (64 cols) + fused log_softmax
    gemm_tc_kernel<64><<<gemm_blocks, 256, smem64>>>(p_a, p_W2h, p_W2l, p_dis, p_h, N);
    agg_lsm_kernel<<<agg_blocks, T>>>(p_h, p_rowptr, p_colsrc, p_dis, b2, out, N);
}

// round 17
// speedup vs baseline: 1.4605x; 1.0001x over previous
#include <cuda_runtime.h>
#include <cuda_bf16.h>
#include <mma.h>
#include <math.h>

using namespace nvcuda;

#define NN   100000
#define EE   1600000
#define DIM  128

// Scratch (static device globals: no allocations allowed; zero-initialized)
__device__ float g_dis[NN];
__device__ float g_h [(size_t)NN * DIM];   // hs = (A@W)*dis of current layer
__device__ float g_a [(size_t)NN * DIM];   // combined activation (next layer input)
__device__ int   g_cnt[NN];                // in-degree histogram (re-zeroed each run)
__device__ int   g_rowptr[NN + 1];
__device__ int   g_cursor[NN];
__device__ int   g_colsrc[EE];
__device__ int   g_blocksum[1024];
// Split weights (bf16 hi/lo)
__device__ __nv_bfloat16 g_W0h[16384], g_W0l[16384];
__device__ __nv_bfloat16 g_W1h[16384], g_W1l[16384];
__device__ __nv_bfloat16 g_W2h[8192],  g_W2l[8192];

__device__ __forceinline__ void split_bf16(float v, __nv_bfloat16& h, __nv_bfloat16& l) {
    h = __float2bfloat16(v);
    l = __float2bfloat16(v - __bfloat162float(h));
}

// ---------------------------------------------------------------------------
// Weight split: W(fp32) -> Wh + Wl (bf16)
// ---------------------------------------------------------------------------
__global__ void split_w_kernel(const float* __restrict__ W, __nv_bfloat16* __restrict__ Wh,
                               __nv_bfloat16* __restrict__ Wl, int n) {
    int i = blockIdx.x * blockDim.x + threadIdx.x;
    if (i < n) {
        __nv_bfloat16 h, l;
        split_bf16(W[i], h, l);
        Wh[i] = h; Wl[i] = l;
    }
}

// in-degree histogram, vectorized: 4 edges per thread via int4
__global__ void count_kernel(const int* __restrict__ dst, int* cnt, int e) {
    int i = blockIdx.x * blockDim.x + threadIdx.x;
    int base = i * 4;
    if (base + 3 < e) {
        int4 d = *(const int4*)(dst + base);
        atomicAdd(&cnt[d.x], 1);
        atomicAdd(&cnt[d.y], 1);
        atomicAdd(&cnt[d.z], 1);
        atomicAdd(&cnt[d.w], 1);
    } else {
        for (int j = base; j < e; j++) atomicAdd(&cnt[dst[j]], 1);
    }
}

// dis = rsqrt(deg+1)
__global__ void dis_kernel(const int* __restrict__ cnt, float* __restrict__ dis, int n) {
    int i = blockIdx.x * blockDim.x + threadIdx.x;
    if (i < n) dis[i] = rsqrtf((float)cnt[i] + 1.0f);
}

// ---------------------------------------------------------------------------
// Multi-block exclusive scan + CSR fill
// ---------------------------------------------------------------------------
__global__ __launch_bounds__(1024) void scan_block_kernel(const int* __restrict__ cnt,
                                                          int* __restrict__ rowptr,
                                                          int* __restrict__ blocksum, int n) {
    __shared__ int wsum[32];
    const int tid = threadIdx.x, lane = tid & 31, wid = tid >> 5;
    int i = blockIdx.x * 1024 + tid;
    int v = (i < n) ? cnt[i] : 0;
    int x = v;
#pragma unroll
    for (int off = 1; off < 32; off <<= 1) {
        int t = __shfl_up_sync(0xffffffffu, x, off);
        if (lane >= off) x += t;
    }
    if (lane == 31) wsum[wid] = x;
    __syncthreads();
    if (wid == 0) {
        int w = wsum[lane];
#pragma unroll
        for (int off = 1; off < 32; off <<= 1) {
            int t = __shfl_up_sync(0xffffffffu, w, off);
            if (lane >= off) w += t;
        }
        wsum[lane] = w;
    }
    __syncthreads();
    int excl = x - v + (wid ? wsum[wid - 1] : 0);
    if (i < n) rowptr[i] = excl;
    if (tid == 1023) blocksum[blockIdx.x] = wsum[31];
}

__global__ void scan_carry_kernel(int* blocksum, int nb) {
    if (threadIdx.x == 0) {
        int acc = 0;
        for (int i = 0; i < nb; i++) { int v = blocksum[i]; blocksum[i] = acc; acc += v; }
    }
}

__global__ void scan_add_kernel(int* __restrict__ rowptr, const int* __restrict__ blocksum,
                                int* __restrict__ cnt, int* __restrict__ cur, int n, int e) {
    int i = blockIdx.x * blockDim.x + threadIdx.x;
    if (i < n) {
        int r = rowptr[i] + blocksum[i >> 10];
        rowptr[i] = r;
        cur[i]    = r;
        cnt[i]    = 0;
    }
    if (i == 0) rowptr[n] = e;
}

// colsrc fill, vectorized: 4 edges per thread
__global__ void fill_kernel(const int* __restrict__ src, const int* __restrict__ dst,
                            int* __restrict__ cur, int* __restrict__ colsrc, int e) {
    int i = blockIdx.x * blockDim.x + threadIdx.x;
    int base = i * 4;
    if (base + 3 < e) {
        int4 d = *(const int4*)(dst + base);
        int4 s = *(const int4*)(src + base);
        colsrc[atomicAdd(&cur[d.x], 1)] = s.x;
        colsrc[atomicAdd(&cur[d.y], 1)] = s.y;
        colsrc[atomicAdd(&cur[d.z], 1)] = s.z;
        colsrc[atomicAdd(&cur[d.w], 1)] = s.w;
    } else {
        for (int j = base; j < e; j++)
            colsrc[atomicAdd(&cur[dst[j]], 1)] = src[j];
    }
}

// ---------------------------------------------------------------------------
// Persistent tensor-core GEMM:
//   C = A[M,128] @ W[128,BN] ; hs = C * dis[row]
// grid = 296 (2 CTAs/SM); each CTA stages W (hi/lo) in smem ONCE, then loops
// over tiles. A split per 16-k stage, double-buffered. Epilogue staged through
// the A-buffer region in 4 x 32-row chunks (keeps W resident across tiles).
// ---------------------------------------------------------------------------
template <int BN>
__global__ __launch_bounds__(256, 2) void gemm_tc_kernel(
    const float* __restrict__ A,
    const __nv_bfloat16* __restrict__ Bh_g,
    const __nv_bfloat16* __restrict__ Bl_g,
    const float* __restrict__ dis,
    float* __restrict__ hs_out, int M, int numTiles)
{
    constexpr int WN  = BN / 2;
    constexpr int FN  = WN / 16;
    constexpr int LDA = 24;
    constexpr int LDB = BN + 8;
    constexpr int ASZ = 128 * LDA;

    extern __shared__ __align__(16) unsigned char smem_raw[];
    __nv_bfloat16* Ab = (__nv_bfloat16*)smem_raw;        // 4 buffers: h0,l0,h1,l1 (24KB)
    __nv_bfloat16* Bh = Ab + 4 * ASZ;
    __nv_bfloat16* Bl = Bh + 128 * LDB;

    const int tid  = threadIdx.x;
    const int wid  = tid >> 5;
    const int wm   = wid & 3;
    const int wn   = wid >> 2;

    // Stage full W (hi/lo) once per CTA
    constexpr int ELEMS = 128 * BN;
    for (int e = tid * 8; e < ELEMS; e += 256 * 8) {
        int r = e / BN, c = e % BN;
        *(uint4*)&Bh[r * LDB + c] = *(const uint4*)&Bh_g[e];
        *(uint4*)&Bl[r * LDB + c] = *(const uint4*)&Bl_g[e];
    }
    __syncthreads();

    const int ar = tid >> 1;
    const int ak = (tid & 1) * 8;

    for (int t = blockIdx.x; t < numTiles; t += gridDim.x) {
        const int row0 = t * 128;
        const int arow = row0 + ar;

        wmma::fragment<wmma::accumulator, 16, 16, 16, float> acc[2][FN];
#pragma unroll
        for (int i = 0; i < 2; i++)
#pragma unroll
            for (int j = 0; j < FN; j++) wmma::fill_fragment(acc[i][j], 0.f);

        float4 v0 = make_float4(0.f, 0.f, 0.f, 0.f), v1 = v0;
        if (arow < M) {
            v0 = *(const float4*)(A + (size_t)arow * 128 + ak);
            v1 = *(const float4*)(A + (size_t)arow * 128 + ak + 4);
        }

        for (int s = 0; s < 8; s++) {
            __nv_bfloat16* pAh = Ab + (s & 1) * 2 * ASZ;
            __nv_bfloat16* pAl = pAh + ASZ;
            {
                __nv_bfloat16 h, l;
                split_bf16(v0.x, h, l); pAh[ar * LDA + ak + 0] = h; pAl[ar * LDA + ak + 0] = l;
                split_bf16(v0.y, h, l); pAh[ar * LDA + ak + 1] = h; pAl[ar * LDA + ak + 1] = l;
                split_bf16(v0.z, h, l); pAh[ar * LDA + ak + 2] = h; pAl[ar * LDA + ak + 2] = l;
                split_bf16(v0.w, h, l); pAh[ar * LDA + ak + 3] = h; pAl[ar * LDA + ak + 3] = l;
                split_bf16(v1.x, h, l); pAh[ar * LDA + ak + 4] = h; pAl[ar * LDA + ak + 4] = l;
                split_bf16(v1.y, h, l); pAh[ar * LDA + ak + 5] = h; pAl[ar * LDA + ak + 5] = l;
                split_bf16(v1.z, h, l); pAh[ar * LDA + ak + 6] = h; pAl[ar * LDA + ak + 6] = l;
                split_bf16(v1.w, h, l); pAh[ar * LDA + ak + 7] = h; pAl[ar * LDA + ak + 7] = l;
            }
            __syncthreads();

            if (s < 7 && arow < M) {
                v0 = *(const float4*)(A + (size_t)arow * 128 + (s + 1) * 16 + ak);
                v1 = *(const float4*)(A + (size_t)arow * 128 + (s + 1) * 16 + ak + 4);
            }

            wmma::fragment<wmma::matrix_a, 16, 16, 16, __nv_bfloat16, wmma::row_major> fa_h[2], fa_l[2];
#pragma unroll
            for (int i = 0; i < 2; i++) {
                wmma::load_matrix_sync(fa_h[i], pAh + (wm * 32 + i * 16) * LDA, LDA);
                wmma::load_matrix_sync(fa_l[i], pAl + (wm * 32 + i * 16) * LDA, LDA);
            }
#pragma unroll
            for (int j = 0; j < FN; j++) {
                wmma::fragment<wmma::matrix_b, 16, 16, 16, __nv_bfloat16, wmma::row_major> fb_h, fb_l;
                wmma::load_matrix_sync(fb_h, Bh + (s * 16) * LDB + wn * WN + j * 16, LDB);
                wmma::load_matrix_sync(fb_l, Bl + (s * 16) * LDB + wn * WN + j * 16, LDB);
#pragma unroll
                for (int i = 0; i < 2; i++) {
                    wmma::mma_sync(acc[i][j], fa_h[i], fb_h, acc[i][j]);
                    wmma::mma_sync(acc[i][j], fa_h[i], fb_l, acc[i][j]);
                    wmma::mma_sync(acc[i][j], fa_l[i], fb_h, acc[i][j]);
                }
            }
        }
        __syncthreads();   // mainloop done; A buffers free for epilogue staging

        // Epilogue: 4 chunks of 32 rows through the A-buffer region (<=16KB each)
        float* Cs = (float*)smem_raw;
        constexpr int QB = BN / 4;
#pragma unroll
        for (int c = 0; c < 4; c++) {
            if (wm == c) {
#pragma unroll
                for (int i = 0; i < 2; i++)
#pragma unroll
                    for (int j = 0; j < FN; j++)
                        wmma::store_matrix_sync(Cs + (i * 16) * BN + wn * WN + j * 16,
                                                acc[i][j], BN, wmma::mem_row_major);
            }
            __syncthreads();
            for (int idx = tid; idx < 32 * QB; idx += 256) {
                int r = idx / QB, col = (idx % QB) * 4;
                int row = row0 + c * 32 + r;
                if (row < M) {
                    float dd = __ldg(dis + row);
                    float4 o = *(float4*)&Cs[r * BN + col];
                    o.x *= dd; o.y *= dd; o.z *= dd; o.w *= dd;
                    *(float4*)(hs_out + (size_t)row * BN + col) = o;
                }
            }
            __syncthreads();
        }
    }
}

// ---------------------------------------------------------------------------
// Aggregation + combine, VECTORIZED: one warp per node, float4 per lane.
// ---------------------------------------------------------------------------
__device__ __forceinline__ void f4_add(float4& a, const float4 b) {
    a.x += b.x; a.y += b.y; a.z += b.z; a.w += b.w;
}

__global__ __launch_bounds__(256) void agg_combine_kernel(
    const float* __restrict__ hs, const int* __restrict__ rowptr,
    const int* __restrict__ colsrc, const float* __restrict__ dis,
    const float* __restrict__ bias, float* __restrict__ outA, int n)
{
    int node = (blockIdx.x * 256 + threadIdx.x) >> 5;
    int lane = threadIdx.x & 31;
    if (node >= n) return;

    const float4* hs4 = (const float4*)hs;      // row stride = 32 float4
    int beg = __ldg(rowptr + node);
    int end = __ldg(rowptr + node + 1);

    float4 a0 = __ldg(hs4 + (size_t)node * 32 + lane);   // self-loop term
    float4 a1 = make_float4(0.f, 0.f, 0.f, 0.f), a2 = a1, a3 = a1;

    int p = beg;
    for (; p + 4 <= end; p += 4) {
        int i0 = __ldg(colsrc + p + 0);
        int i1 = __ldg(colsrc + p + 1);
        int i2 = __ldg(colsrc + p + 2);
        int i3 = __ldg(colsrc + p + 3);
        float4 v0 = __ldg(hs4 + (size_t)i0 * 32 + lane);
        float4 v1 = __ldg(hs4 + (size_t)i1 * 32 + lane);
        float4 v2 = __ldg(hs4 + (size_t)i2 * 32 + lane);
        float4 v3 = __ldg(hs4 + (size_t)i3 * 32 + lane);
        f4_add(a0, v0); f4_add(a1, v1); f4_add(a2, v2); f4_add(a3, v3);
    }
    for (; p < end; ++p)
        f4_add(a0, __ldg(hs4 + (size_t)__ldg(colsrc + p) * 32 + lane));

    f4_add(a0, a1); f4_add(a2, a3); f4_add(a0, a2);

    float dd = __ldg(dis + node);
    float4 bb = __ldg((const float4*)bias + lane);
    float4 o;
    o.x = fmaxf(fmaf(dd, a0.x, bb.x), 0.f);
    o.y = fmaxf(fmaf(dd, a0.y, bb.y), 0.f);
    o.z = fmaxf(fmaf(dd, a0.z, bb.z), 0.f);
    o.w = fmaxf(fmaf(dd, a0.w, bb.w), 0.f);
    ((float4*)outA)[(size_t)node * 32 + lane] = o;
}

// ---------------------------------------------------------------------------
// Fused final layer, VECTORIZED: warp per node, float2 per lane (F=64).
// ---------------------------------------------------------------------------
__global__ __launch_bounds__(256) void agg_lsm_kernel(
    const float* __restrict__ hs, const int* __restrict__ rowptr,
    const int* __restrict__ colsrc, const float* __restrict__ dis,
    const float* __restrict__ bias, float* __restrict__ out, int n)
{
    int node = (blockIdx.x * 256 + threadIdx.x) >> 5;
    int lane = threadIdx.x & 31;
    if (node >= n) return;

    const float2* hs2 = (const float2*)hs;      // row stride = 32 float2
    int beg = __ldg(rowptr + node);
    int end = __ldg(rowptr + node + 1);

    float2 a0 = __ldg(hs2 + (size_t)node * 32 + lane);
    float2 a1 = make_float2(0.f, 0.f), a2 = a1, a3 = a1;

    int p = beg;
    for (; p + 4 <= end; p += 4) {
        int i0 = __ldg(colsrc + p + 0);
        int i1 = __ldg(colsrc + p + 1);
        int i2 = __ldg(colsrc + p + 2);
        int i3 = __ldg(colsrc + p + 3);
        float2 v0 = __ldg(hs2 + (size_t)i0 * 32 + lane);
        float2 v1 = __ldg(hs2 + (size_t)i1 * 32 + lane);
        float2 v2 = __ldg(hs2 + (size_t)i2 * 32 + lane);
        float2 v3 = __ldg(hs2 + (size_t)i3 * 32 + lane);
        a0.x += v0.x; a0.y += v0.y; a1.x += v1.x; a1.y += v1.y;
        a2.x += v2.x; a2.y += v2.y; a3.x += v3.x; a3.y += v3.y;
    }
    for (; p < end; ++p) {
        float2 v = __ldg(hs2 + (size_t)__ldg(colsrc + p) * 32 + lane);
        a0.x += v.x; a0.y += v.y;
    }
    float sx = (a0.x + a1.x) + (a2.x + a3.x);
    float sy = (a0.y + a1.y) + (a2.y + a3.y);

    float dd = __ldg(dis + node);
    float2 bb = __ldg((const float2*)bias + lane);
    float v0 = fmaxf(fmaf(dd, sx, bb.x), 0.f);
    float v1 = fmaxf(fmaf(dd, sy, bb.y), 0.f);

    float m = fmaxf(v0, v1);
#pragma unroll
    for (int off = 16; off > 0; off >>= 1)
        m = fmaxf(m, __shfl_xor_sync(0xffffffffu, m, off));
    float s = expf(v0 - m) + expf(v1 - m);
#pragma unroll
    for (int off = 16; off > 0; off >>= 1)
        s += __shfl_xor_sync(0xffffffffu, s, off);
    float ls = logf(s);

    float2 o = make_float2(v0 - m - ls, v1 - m - ls);
    ((float2*)out)[(size_t)node * 32 + lane] = o;
}

// ---------------------------------------------------------------------------
// Launch (single stream; gemm0 is the 4th kernel launch for ncu capture)
// ---------------------------------------------------------------------------
extern "C" void kernel_launch(void* const* d_in, const int* in_sizes, int n_in,
                              void* d_out, int out_size) {
    const float* x  = (const float*)d_in[0];
    const int*   ei = (const int*)d_in[1];
    const float* W0 = (const float*)d_in[2];
    const float* b0 = (const float*)d_in[3];
    const float* W1 = (const float*)d_in[4];
    const float* b1 = (const float*)d_in[5];
    const float* W2 = (const float*)d_in[6];
    const float* b2 = (const float*)d_in[7];
    float* out = (float*)d_out;

    const int E = in_sizes[1] / 2;
    const int N = in_sizes[0] / DIM;
    const int* src = ei;
    const int* dst = ei + E;

    float *p_dis, *p_h, *p_a;
    int *p_cnt, *p_rowptr, *p_cursor, *p_colsrc, *p_blocksum;
    __nv_bfloat16 *p_W0h, *p_W0l, *p_W1h, *p_W1l, *p_W2h, *p_W2l;
    cudaGetSymbolAddress((void**)&p_dis,      g_dis);
    cudaGetSymbolAddress((void**)&p_h,        g_h);
    cudaGetSymbolAddress((void**)&p_a,        g_a);
    cudaGetSymbolAddress((void**)&p_cnt,      g_cnt);
    cudaGetSymbolAddress((void**)&p_rowptr,   g_rowptr);
    cudaGetSymbolAddress((void**)&p_cursor,   g_cursor);
    cudaGetSymbolAddress((void**)&p_colsrc,   g_colsrc);
    cudaGetSymbolAddress((void**)&p_blocksum, g_blocksum);
    cudaGetSymbolAddress((void**)&p_W0h, g_W0h); cudaGetSymbolAddress((void**)&p_W0l, g_W0l);
    cudaGetSymbolAddress((void**)&p_W1h, g_W1h); cudaGetSymbolAddress((void**)&p_W1l, g_W1l);
    cudaGetSymbolAddress((void**)&p_W2h, g_W2h); cudaGetSymbolAddress((void**)&p_W2l, g_W2l);

    const int smem128 = (4 * 128 * 24 + 2 * 128 * 136) * 2;   // 94208 B
    const int smem64  = (4 * 128 * 24 + 2 * 128 * 72)  * 2;   // 61440 B
    cudaFuncSetAttribute(gemm_tc_kernel<128>, cudaFuncAttributeMaxDynamicSharedMemorySize, smem128);
    cudaFuncSetAttribute(gemm_tc_kernel<64>,  cudaFuncAttributeMaxDynamicSharedMemorySize, smem64);

    const int T = 256;
    const int nb = (N + 1023) / 1024;
    const int numTiles = (N + 127) / 128;
    const int pgrid = numTiles < 296 ? numTiles : 296;   // persistent: 2 CTAs/SM
    const int agg_blocks = (N * 32 + T - 1) / T;         // warp per node
    const int e4 = (E + 3) / 4;

    // 1-3: gemm0 prerequisites
    count_kernel<<<(e4 + T - 1) / T, T>>>(dst, p_cnt, E);                    // 1
    dis_kernel<<<(N + T - 1) / T, T>>>(p_cnt, p_dis, N);                     // 2
    split_w_kernel<<<64, 256>>>(W0, p_W0h, p_W0l, 16384);                    // 3

    // 4: layer-0 GEMM (ncu captures the 4th launch)
    gemm_tc_kernel<128><<<pgrid, 256, smem128>>>(x, p_W0h, p_W0l,
                                                 p_dis, p_h, N, numTiles);   // 4

    // remaining weight splits + CSR build
    split_w_kernel<<<64, 256>>>(W1, p_W1h, p_W1l, 16384);
    split_w_kernel<<<32, 256>>>(W2, p_W2h, p_W2l, 8192);
    scan_block_kernel<<<nb, 1024>>>(p_cnt, p_rowptr, p_blocksum, N);
    scan_carry_kernel<<<1, 32>>>(p_blocksum, nb);
    scan_add_kernel<<<(N + T - 1) / T, T>>>(p_rowptr, p_blocksum, p_cnt, p_cursor, N, E);
    fill_kernel<<<(e4 + T - 1) / T, T>>>(src, dst, p_cursor, p_colsrc, E);

    // Layer 0 combine
    agg_combine_kernel<<<agg_blocks, T>>>(p_h, p_rowptr, p_colsrc, p_dis, b0, p_a, N);

    // Layer 1
    gemm_tc_kernel<128><<<pgrid, 256, smem128>>>(p_a, p_W1h, p_W1l, p_dis, p_h, N, numTiles);
    agg_combine_kernel<<<agg_blocks, T>>>(p_h, p_rowptr, p_colsrc, p_dis, b1, p_a, N);

    // Layer 2 (64 cols) + fused log_softmax
    gemm_tc_kernel<64><<<pgrid, 256, smem64>>>(p_a, p_W2h, p_W2l, p_dis, p_h, N, numTiles);
    agg_lsm_kernel<<<agg_blocks, T>>>(p_h, p_rowptr, p_colsrc, p_dis, b2, out, N);
}